// round 1
// baseline (speedup 1.0000x reference)
#include <cuda_runtime.h>
#include <math.h>

// ---------------------------------------------------------------------------
// Problem constants (fixed shapes)
// ---------------------------------------------------------------------------
constexpr int Bc = 4, Mc = 8, NPc = 4096, Hc = 256, FDc = 512, Sc = 128;
constexpr int BNP  = Bc * NPc;        // 16384 point rows
constexpr int BMNP = Bc * Mc * NPc;   // 131072 view rows
constexpr int NSEG = Bc * Sc + 1;     // 513 (+1 dump segment)

// ---------------------------------------------------------------------------
// Device scratch (static: no allocations allowed)
// ---------------------------------------------------------------------------
__device__ float g_pp[BNP * Hc];                 // 16.8 MB
__device__ float g_vp[(size_t)BMNP * Hc];        // 134 MB
__device__ float g_attn[BMNP];                   // 0.5 MB
__device__ float g_weighted[BNP * Hc];           // 16.8 MB
__device__ float g_wvp[BNP * Hc];                // 16.8 MB
__device__ float g_cnt[NSEG];
__device__ float g_asum[NSEG * Mc];
__device__ float g_fsum[NSEG * Hc];

// ---------------------------------------------------------------------------
// Fused GEMM + bias + LayerNorm (+ReLU / +a2-dot+sigmoid) kernel.
//   Y_pre[r, n] = sum_k X[r, k] * W[k, n] + bias[n]
//   EPI 0: Y = relu(LN(Y_pre))            -> Y [rows, N]
//   EPI 1: h = relu(LN(Y_pre)); Y[r] = sigmoid(h . a2w + a2b)  (attn path)
//   EPI 2: Y = LN(Y_pre)                  -> Y [rows, N]
// KTOT==512 concatenates X1 (k<256) and X2 (k>=256), both row-stride 256.
// BCAST maps view-row r=(b*M+m)*NP+p -> point-row b*NP+p for X1 (pp broadcast).
// Block: 512 threads, TR rows x full N. Micro-tile: 8 rows x 4 cols / thread.
// ---------------------------------------------------------------------------
template<int N, int KTOT, int EPI, bool BCAST>
__global__ __launch_bounds__(512)
void gemm_ln_kernel(const float* __restrict__ X1, const float* __restrict__ X2,
                    const float* __restrict__ Wm, const float* __restrict__ bias,
                    const float* __restrict__ gamma, const float* __restrict__ beta,
                    const float* __restrict__ a2w, const float* __restrict__ a2b,
                    float* __restrict__ Y)
{
    constexpr int TX = N / 4;          // threads along N (4 cols each)
    constexpr int TY = 512 / TX;       // thread rows
    constexpr int TR = 8 * TY;         // rows per block (64 for N=256, 32 for N=512)
    constexpr int KC = 32;             // k-chunk
    constexpr int XP = 36;             // sX row stride (float4-aligned pad)
    constexpr int EP = N + 4;          // sE row stride

    extern __shared__ float sm[];
    float* sX = sm;                    // TR * XP
    float* sW = sm + TR * XP;          // KC * N
    float* sE = sW + KC * N;           // TR * EP

    const int tid = threadIdx.x;
    const int tx = tid % TX;
    const int ty = tid / TX;
    const int r0 = blockIdx.x * TR;

    size_t x1base;
    if (BCAST) {
        int b = r0 / (Mc * NPc);
        int p = r0 % NPc;
        x1base = ((size_t)b * NPc + p) * 256;  // NP % TR == 0, tile stays in one (b,m)
    } else {
        x1base = (size_t)r0 * 256;
    }
    const size_t x2base = (size_t)r0 * 256;

    float acc[8][4];
#pragma unroll
    for (int i = 0; i < 8; i++)
#pragma unroll
        for (int j = 0; j < 4; j++) acc[i][j] = 0.f;

    for (int kc = 0; kc < KTOT; kc += KC) {
        // ---- load X tile [TR x KC] (row-major, stride 256 floats) ----
        const float* Xs;
        size_t xb;
        if (KTOT == 512 && kc >= 256) { Xs = X2; xb = x2base + (size_t)(kc - 256); }
        else                          { Xs = X1; xb = x1base + (size_t)kc; }
        if (TR == 64) {
            int row = tid >> 3, k4 = tid & 7;
            float4 v = *reinterpret_cast<const float4*>(Xs + xb + (size_t)row * 256 + k4 * 4);
            *reinterpret_cast<float4*>(&sX[row * XP + k4 * 4]) = v;
        } else {
            if (tid < TR * 8) {
                int row = tid >> 3, k4 = tid & 7;
                float4 v = *reinterpret_cast<const float4*>(Xs + xb + (size_t)row * 256 + k4 * 4);
                *reinterpret_cast<float4*>(&sX[row * XP + k4 * 4]) = v;
            }
        }
        // ---- load W tile [KC x N] (contiguous block of W) ----
        const float* Wp = Wm + (size_t)kc * N;
#pragma unroll
        for (int idx = tid; idx < KC * N / 4; idx += 512) {
            float4 v = *reinterpret_cast<const float4*>(Wp + (size_t)idx * 4);
            *reinterpret_cast<float4*>(&sW[idx * 4]) = v;
        }
        __syncthreads();

        // ---- mainloop: 32 FFMA per k per thread ----
#pragma unroll
        for (int k = 0; k < KC; k++) {
            float4 w = *reinterpret_cast<const float4*>(&sW[k * N + tx * 4]);
#pragma unroll
            for (int i = 0; i < 8; i++) {
                float x = sX[(ty + TY * i) * XP + k];   // warp-broadcast
                acc[i][0] += x * w.x;
                acc[i][1] += x * w.y;
                acc[i][2] += x * w.z;
                acc[i][3] += x * w.w;
            }
        }
        __syncthreads();
    }

    // ---- bias add, stage rows to shared for the LN row reduction ----
    float4 bb = *reinterpret_cast<const float4*>(bias + tx * 4);
#pragma unroll
    for (int i = 0; i < 8; i++) {
        int r = ty + TY * i;
        float4 o;
        o.x = acc[i][0] + bb.x; o.y = acc[i][1] + bb.y;
        o.z = acc[i][2] + bb.z; o.w = acc[i][3] + bb.w;
        *reinterpret_cast<float4*>(&sE[r * EP + tx * 4]) = o;
    }
    __syncthreads();

    // ---- per-row LayerNorm epilogue: 16 warps, TR/16 rows per warp ----
    const int lane = tid & 31, wid = tid >> 5;
    constexpr int RPW = TR / 16;
    constexpr int CPL = N / 32;        // cols per lane (8 or 16)
#pragma unroll
    for (int rr = 0; rr < RPW; rr++) {
        int r = wid * RPW + rr;
        int c0 = lane * CPL;
        float v[CPL];
        float s = 0.f, s2 = 0.f;
#pragma unroll
        for (int q = 0; q < CPL / 4; q++) {
            float4 t = *reinterpret_cast<const float4*>(&sE[r * EP + c0 + q * 4]);
            v[q*4+0]=t.x; v[q*4+1]=t.y; v[q*4+2]=t.z; v[q*4+3]=t.w;
            s  += t.x + t.y + t.z + t.w;
            s2 += t.x*t.x + t.y*t.y + t.z*t.z + t.w*t.w;
        }
#pragma unroll
        for (int o = 16; o > 0; o >>= 1) {
            s  += __shfl_xor_sync(0xffffffffu, s, o);
            s2 += __shfl_xor_sync(0xffffffffu, s2, o);
        }
        float mean = s * (1.f / N);
        float var  = s2 * (1.f / N) - mean * mean;
        float rstd = rsqrtf(var + 1e-5f);

        if (EPI == 1) {
            float dot = 0.f;
#pragma unroll
            for (int q = 0; q < CPL; q++) {
                int c = c0 + q;
                float y = (v[q] - mean) * rstd * gamma[c] + beta[c];
                y = fmaxf(y, 0.f);
                dot += y * a2w[c];
            }
#pragma unroll
            for (int o = 16; o > 0; o >>= 1)
                dot += __shfl_xor_sync(0xffffffffu, dot, o);
            if (lane == 0) {
                float a = dot + a2b[0];
                Y[r0 + r] = 1.f / (1.f + expf(-a));
            }
        } else {
#pragma unroll
            for (int q = 0; q < CPL / 4; q++) {
                float4 gg = *reinterpret_cast<const float4*>(gamma + c0 + q * 4);
                float4 be = *reinterpret_cast<const float4*>(beta  + c0 + q * 4);
                float4 o;
                o.x = (v[q*4+0]-mean)*rstd*gg.x + be.x;
                o.y = (v[q*4+1]-mean)*rstd*gg.y + be.y;
                o.z = (v[q*4+2]-mean)*rstd*gg.z + be.z;
                o.w = (v[q*4+3]-mean)*rstd*gg.w + be.w;
                if (EPI == 0) {
                    o.x = fmaxf(o.x, 0.f); o.y = fmaxf(o.y, 0.f);
                    o.z = fmaxf(o.z, 0.f); o.w = fmaxf(o.w, 0.f);
                }
                *reinterpret_cast<float4*>(&Y[(size_t)(r0 + r) * N + c0 + q * 4]) = o;
            }
        }
    }
}

// ---------------------------------------------------------------------------
// Zero the segment-sum arrays.
// ---------------------------------------------------------------------------
__global__ __launch_bounds__(256) void zero_seg_kernel()
{
    int i = blockIdx.x * 256 + threadIdx.x;
    if (i < NSEG * Hc) g_fsum[i] = 0.f;
    if (i < NSEG * Mc) g_asum[i] = 0.f;
    if (i < NSEG)      g_cnt[i]  = 0.f;
}

// ---------------------------------------------------------------------------
// Segment sums: cnt[seg], asum[seg][m] (attn), fsum[seg][h] (pp).
// One block per (b,p); 256 lanes cover H.
// ---------------------------------------------------------------------------
__global__ __launch_bounds__(256)
void seg_sum_kernel(const int* __restrict__ sp, const float* __restrict__ attn)
{
    int bp = blockIdx.x;
    int b = bp / NPc, p = bp - b * NPc;
    int sid = sp[bp];
    int seg = (sid >= 0) ? (sid + b * Sc) : (Bc * Sc);
    int t = threadIdx.x;
    atomicAdd(&g_fsum[seg * Hc + t], g_pp[(size_t)bp * Hc + t]);
    if (t == 0) atomicAdd(&g_cnt[seg], 1.f);
    if (t < Mc) atomicAdd(&g_asum[seg * Mc + t], attn[((size_t)(b * Mc + t)) * NPc + p]);
}

// ---------------------------------------------------------------------------
// Fused: cosine-sim refinement + softmax over views + weighted view pooling.
// One block per (b,p); 256 lanes cover H / the vf feature dim.
// ---------------------------------------------------------------------------
__global__ __launch_bounds__(256)
void refine_weighted_kernel(const int* __restrict__ sp, const float* __restrict__ vf)
{
    int bp = blockIdx.x;
    int b = bp / NPc, p = bp - b * NPc;
    int t = threadIdx.x;
    int lane = t & 31, wid = t >> 5;
    int sid = sp[bp];
    bool valid = sid >= 0;
    int seg = valid ? (sid + b * Sc) : (Bc * Sc);
    float cnt = fmaxf(g_cnt[seg], 1.f);
    float inv = 1.f / cnt;

    float f  = g_pp[(size_t)bp * Hc + t];
    float fm = g_fsum[seg * Hc + t] * inv;
    float d = f * fm, nf = f * f, nm = fm * fm;
#pragma unroll
    for (int o = 16; o > 0; o >>= 1) {
        d  += __shfl_xor_sync(0xffffffffu, d,  o);
        nf += __shfl_xor_sync(0xffffffffu, nf, o);
        nm += __shfl_xor_sync(0xffffffffu, nm, o);
    }
    __shared__ float sd[8], sf[8], sn[8];
    __shared__ float wts[Mc];
    if (lane == 0) { sd[wid] = d; sf[wid] = nf; sn[wid] = nm; }
    __syncthreads();
    if (t == 0) {
        float D = 0.f, F = 0.f, Nm = 0.f;
#pragma unroll
        for (int i = 0; i < 8; i++) { D += sd[i]; F += sf[i]; Nm += sn[i]; }
        float sim = D / (fmaxf(sqrtf(F), 1e-8f) * fmaxf(sqrtf(Nm), 1e-8f));
        float rv[Mc];
        float mx = -1e30f;
#pragma unroll
        for (int m = 0; m < Mc; m++) {
            float a  = g_attn[((size_t)(b * Mc + m)) * NPc + p];
            float am = g_asum[seg * Mc + m] * inv;
            float rf = valid ? (am + (a - am) * sim) : a;
            rv[m] = rf;
            mx = fmaxf(mx, rf);
        }
        float ssum = 0.f;
#pragma unroll
        for (int m = 0; m < Mc; m++) { rv[m] = expf(rv[m] - mx); ssum += rv[m]; }
        float is = 1.f / ssum;
#pragma unroll
        for (int m = 0; m < Mc; m++) wts[m] = rv[m] * is;
    }
    __syncthreads();

    float acc = 0.f;
#pragma unroll
    for (int m = 0; m < Mc; m++)
        acc += wts[m] * vf[((size_t)(b * Mc + m) * NPc + p) * 256 + t];
    g_weighted[(size_t)bp * Hc + t] = acc;
}

// ---------------------------------------------------------------------------
// Launch
// ---------------------------------------------------------------------------
extern "C" void kernel_launch(void* const* d_in, const int* in_sizes, int n_in,
                              void* d_out, int out_size)
{
    (void)in_sizes; (void)n_in; (void)out_size;
    const float* pf   = (const float*)d_in[0];
    const float* vf   = (const float*)d_in[1];
    const int*   spid = (const int*)d_in[2];
    const float* p_W  = (const float*)d_in[3];
    const float* p_b  = (const float*)d_in[4];
    const float* p_g  = (const float*)d_in[5];
    const float* p_be = (const float*)d_in[6];
    const float* v_W  = (const float*)d_in[7];
    const float* v_b  = (const float*)d_in[8];
    const float* v_g  = (const float*)d_in[9];
    const float* v_be = (const float*)d_in[10];
    const float* a1_W = (const float*)d_in[11];
    const float* a1_b = (const float*)d_in[12];
    const float* a_g  = (const float*)d_in[13];
    const float* a_be = (const float*)d_in[14];
    const float* a2_W = (const float*)d_in[15];
    const float* a2_b = (const float*)d_in[16];
    const float* f_W  = (const float*)d_in[17];
    const float* f_b  = (const float*)d_in[18];
    const float* f_g  = (const float*)d_in[19];
    const float* f_be = (const float*)d_in[20];
    float* out = (float*)d_out;

    float *pp, *vp, *attn, *weighted, *wvp;
    cudaGetSymbolAddress((void**)&pp,       g_pp);
    cudaGetSymbolAddress((void**)&vp,       g_vp);
    cudaGetSymbolAddress((void**)&attn,     g_attn);
    cudaGetSymbolAddress((void**)&weighted, g_weighted);
    cudaGetSymbolAddress((void**)&wvp,      g_wvp);

    constexpr int SM256 = (64 * 36 + 32 * 256 + 64 * 260) * 4;   // 108544 B
    constexpr int SM512 = (32 * 36 + 32 * 512 + 32 * 516) * 4;   // 136192 B
    cudaFuncSetAttribute(gemm_ln_kernel<256, 256, 0, false>,
                         cudaFuncAttributeMaxDynamicSharedMemorySize, SM256);
    cudaFuncSetAttribute(gemm_ln_kernel<256, 512, 1, true>,
                         cudaFuncAttributeMaxDynamicSharedMemorySize, SM256);
    cudaFuncSetAttribute(gemm_ln_kernel<512, 512, 2, false>,
                         cudaFuncAttributeMaxDynamicSharedMemorySize, SM512);

    // 1) pp = relu(LN(pf @ p_W + p_b))
    gemm_ln_kernel<256, 256, 0, false><<<BNP / 64, 512, SM256>>>(
        pf, nullptr, p_W, p_b, p_g, p_be, nullptr, nullptr, pp);
    // 2) vp = relu(LN(vf @ v_W + v_b))
    gemm_ln_kernel<256, 256, 0, false><<<BMNP / 64, 512, SM256>>>(
        vf, nullptr, v_W, v_b, v_g, v_be, nullptr, nullptr, vp);
    // 3) attn = sigmoid(relu(LN([pp,vp] @ a1_W + a1_b)) . a2_W + a2_b)
    gemm_ln_kernel<256, 512, 1, true><<<BMNP / 64, 512, SM256>>>(
        pp, vp, a1_W, a1_b, a_g, a_be, a2_W, a2_b, attn);
    // 4) segment sums
    zero_seg_kernel<<<(NSEG * Hc + 255) / 256, 256>>>();
    seg_sum_kernel<<<BNP, 256>>>(spid, attn);
    // 5) refine + softmax + weighted view pooling
    refine_weighted_kernel<<<BNP, 256>>>(spid, vf);
    // 6) wvp = relu(LN(weighted @ v_W + v_b))
    gemm_ln_kernel<256, 256, 0, false><<<BNP / 64, 512, SM256>>>(
        weighted, nullptr, v_W, v_b, v_g, v_be, nullptr, nullptr, wvp);
    // 7) Z = LN([pp,wvp] @ f_W + f_b)  -> output
    gemm_ln_kernel<512, 512, 2, false><<<BNP / 32, 512, SM512>>>(
        pp, wvp, f_W, f_b, f_g, f_be, nullptr, nullptr, out);
}

// round 4
// speedup vs baseline: 2.2837x; 2.2837x over previous
#include <cuda_runtime.h>
#include <cuda_fp16.h>
#include <math.h>
#include <stdint.h>

// ---------------------------------------------------------------------------
// Problem constants
// ---------------------------------------------------------------------------
constexpr int Bc = 4, Mc = 8, NPc = 4096, Hc = 256, FDc = 512, Sc = 128;
constexpr int BNP  = Bc * NPc;        // 16384
constexpr int BMNP = Bc * Mc * NPc;   // 131072
constexpr int NSEG = Bc * Sc + 1;     // 513

// ---------------------------------------------------------------------------
// Device scratch
// ---------------------------------------------------------------------------
__device__ float g_pp[BNP * Hc];
__device__ float g_vp[(size_t)BMNP * Hc];
__device__ float g_attn[BMNP];
__device__ float g_weighted[BNP * Hc];
__device__ float g_wvp[BNP * Hc];
__device__ float g_cnt[NSEG];
__device__ float g_asum[NSEG * Mc];
__device__ float g_fsum[NSEG * Hc];
// transposed + hi/lo split weights: WT[n][k], row length = K, fp16
__device__ __half g_pWT_hi[256 * 256],  g_pWT_lo[256 * 256];
__device__ __half g_vWT_hi[256 * 256],  g_vWT_lo[256 * 256];
__device__ __half g_a1WT_hi[256 * 512], g_a1WT_lo[256 * 512];
__device__ __half g_fWT_hi[512 * 512],  g_fWT_lo[512 * 512];

// ---------------------------------------------------------------------------
// Helpers (base sm_100 ISA only: ldmatrix / mma.sync / cp.async)
// ---------------------------------------------------------------------------
__device__ __forceinline__ uint32_t cvta_smem(const void* p) {
    return (uint32_t)__cvta_generic_to_shared(p);
}
__device__ __forceinline__ void ldsm_x4(uint32_t (&r)[4], uint32_t addr) {
    asm volatile("ldmatrix.sync.aligned.m8n8.x4.shared.b16 {%0,%1,%2,%3}, [%4];"
                 : "=r"(r[0]), "=r"(r[1]), "=r"(r[2]), "=r"(r[3]) : "r"(addr));
}
__device__ __forceinline__ void mma16816(float (&d)[4], const uint32_t (&a)[4],
                                         uint32_t b0, uint32_t b1) {
    asm volatile(
        "mma.sync.aligned.m16n8k16.row.col.f32.f16.f16.f32 "
        "{%0,%1,%2,%3}, {%4,%5,%6,%7}, {%8,%9}, {%0,%1,%2,%3};"
        : "+f"(d[0]), "+f"(d[1]), "+f"(d[2]), "+f"(d[3])
        : "r"(a[0]), "r"(a[1]), "r"(a[2]), "r"(a[3]), "r"(b0), "r"(b1));
}
__device__ __forceinline__ void cp_async16(uint32_t dst, const void* src) {
    asm volatile("cp.async.cg.shared.global [%0], [%1], 16;\n"
                 :: "r"(dst), "l"(src) : "memory");
}
__device__ __forceinline__ void cp_commit() {
    asm volatile("cp.async.commit_group;\n" ::: "memory");
}

// ---------------------------------------------------------------------------
// Weight prep: W[K,N] fp32 -> WT_hi/lo[n*K+k] fp16 split
// ---------------------------------------------------------------------------
template<int K, int N>
__global__ __launch_bounds__(256)
void wt_prep(const float* __restrict__ W, __half* __restrict__ hi,
             __half* __restrict__ lo)
{
    int i = blockIdx.x * 256 + threadIdx.x;
    if (i >= K * N) return;
    int n = i / K, k = i - n * K;
    float x = W[k * N + n];
    __half h = __float2half_rn(x);
    hi[i] = h;
    lo[i] = __float2half_rn(x - __half2float(h));
}

// ---------------------------------------------------------------------------
// mma.sync GEMM + bias + LayerNorm epilogue (fp16 hi/lo Markidis split).
//   D[r,n] = sum_k X[r,k] * W[k,n]
//   EPI 0: Y = relu(LN(D+b))   EPI 1: Y[r] = sigmoid(relu(LN(D+b)).a2w + a2b)
//   EPI 2: Y = LN(D+b)
// 512 threads. N=256: 128 rows/CTA, warp grid 4x4. N=512: 64 rows, 2x8.
// Warp tile 32x64. K chunks of 32 (2 k16 steps), 2-stage cp.async pipeline.
// ---------------------------------------------------------------------------
template<int N, int KTOT, int EPI, bool BCAST>
__global__ __launch_bounds__(512, 1)
void mma_gemm_ln(const float* __restrict__ X1, const float* __restrict__ X2,
                 const __half* __restrict__ WHi, const __half* __restrict__ WLo,
                 const float* __restrict__ bias, const float* __restrict__ gamma,
                 const float* __restrict__ beta, const float* __restrict__ a2w,
                 const float* __restrict__ a2b, float* __restrict__ Y)
{
    constexpr int WN = N / 64;            // warps along N
    constexpr int WM = 16 / WN;           // warps along M
    constexpr int ROWS = WM * 32;         // rows per CTA (128 or 64)
    constexpr int NCH = KTOT / 32;        // K chunks
    constexpr int SST = (2 * ROWS + 2 * N) * 80;   // per-stage smem bytes
    constexpr int FPT = ROWS * 32 / 512;  // A floats per thread (8 or 4)
    constexpr int CPT = N / 64;           // cp.async ops per thread per stage

    extern __shared__ __align__(16) char smem[];
    const uint32_t sb = cvta_smem(smem);

    const int tid = threadIdx.x;
    const int lane = tid & 31, wid = tid >> 5;
    const int wm = wid / WN, wn = wid % WN;
    const int r0 = blockIdx.x * ROWS;

    size_t x1base;
    if (BCAST) {
        int b = r0 / (Mc * NPc);
        int p = r0 % NPc;
        x1base = ((size_t)b * NPc + p) * 256;
    } else {
        x1base = (size_t)r0 * 256;
    }
    const size_t x2base = (size_t)r0 * 256;

    // ---- A global load (one chunk -> FPT floats in regs) ----
    auto ldgA = [&](int kc, float* ar) {
        const float* Xs; size_t xb;
        if (KTOT == 512 && kc >= 8) { Xs = X2; xb = x2base + (size_t)(kc - 8) * 32; }
        else                        { Xs = X1; xb = x1base + (size_t)kc * 32; }
        if (FPT == 8) {
            const float* p = Xs + xb + (size_t)(tid >> 2) * 256 + (tid & 3) * 8;
            float4 v0 = *reinterpret_cast<const float4*>(p);
            float4 v1 = *reinterpret_cast<const float4*>(p + 4);
            ar[0]=v0.x; ar[1]=v0.y; ar[2]=v0.z; ar[3]=v0.w;
            ar[4]=v1.x; ar[5]=v1.y; ar[6]=v1.z; ar[7]=v1.w;
        } else {
            const float* p = Xs + xb + (size_t)(tid >> 3) * 256 + (tid & 7) * 4;
            float4 v0 = *reinterpret_cast<const float4*>(p);
            ar[0]=v0.x; ar[1]=v0.y; ar[2]=v0.z; ar[3]=v0.w;
        }
    };
    // ---- A split + smem store ----
    auto stsA = [&](int s, const float* ar) {
        char* stage = smem + s * SST;
        if (FPT == 8) {
            int row = tid >> 2, coff = (tid & 3) * 16;
            uint32_t hv[4], lv[4];
#pragma unroll
            for (int j = 0; j < 4; j++) {
                __half h0 = __float2half_rn(ar[2*j]);
                __half h1 = __float2half_rn(ar[2*j+1]);
                __half l0 = __float2half_rn(ar[2*j]   - __half2float(h0));
                __half l1 = __float2half_rn(ar[2*j+1] - __half2float(h1));
                hv[j] = __half_as_ushort(h0) | ((uint32_t)__half_as_ushort(h1) << 16);
                lv[j] = __half_as_ushort(l0) | ((uint32_t)__half_as_ushort(l1) << 16);
            }
            *reinterpret_cast<uint4*>(stage + row * 80 + coff) =
                make_uint4(hv[0], hv[1], hv[2], hv[3]);
            *reinterpret_cast<uint4*>(stage + ROWS * 80 + row * 80 + coff) =
                make_uint4(lv[0], lv[1], lv[2], lv[3]);
        } else {
            int row = tid >> 3, coff = (tid & 7) * 8;
            uint32_t hv[2], lv[2];
#pragma unroll
            for (int j = 0; j < 2; j++) {
                __half h0 = __float2half_rn(ar[2*j]);
                __half h1 = __float2half_rn(ar[2*j+1]);
                __half l0 = __float2half_rn(ar[2*j]   - __half2float(h0));
                __half l1 = __float2half_rn(ar[2*j+1] - __half2float(h1));
                hv[j] = __half_as_ushort(h0) | ((uint32_t)__half_as_ushort(h1) << 16);
                lv[j] = __half_as_ushort(l0) | ((uint32_t)__half_as_ushort(l1) << 16);
            }
            *reinterpret_cast<uint2*>(stage + row * 80 + coff) = make_uint2(hv[0], hv[1]);
            *reinterpret_cast<uint2*>(stage + ROWS * 80 + row * 80 + coff) = make_uint2(lv[0], lv[1]);
        }
    };
    // ---- B cp.async (preconverted fp16 hi/lo, [n][KTOT]) ----
    auto cpB = [&](int kc, int s) {
#pragma unroll
        for (int q = 0; q < CPT; q++) {
            int i = tid + q * 512;
            int c = i & 3, pr = (i >> 2) & 1, n = i >> 3;
            const __half* src = (pr ? WLo : WHi) + (size_t)n * KTOT + kc * 32 + c * 8;
            uint32_t dst = sb + s * SST + (uint32_t)(2 * ROWS + pr * N) * 80
                         + (uint32_t)n * 80 + c * 16;
            cp_async16(dst, src);
        }
    };

    float acc[2][8][4];
#pragma unroll
    for (int a = 0; a < 2; a++)
#pragma unroll
        for (int b = 0; b < 8; b++)
#pragma unroll
            for (int c = 0; c < 4; c++) acc[a][b][c] = 0.f;

    float ar[FPT];
    // prologue
    ldgA(0, ar);
    cpB(0, 0); cp_commit();
    stsA(0, ar);
    if (NCH > 1) { ldgA(1, ar); cpB(1, 1); cp_commit(); }

    const int l16 = lane & 15, lh = lane >> 4;

    for (int kc = 0; kc < NCH; kc++) {
        const int cur = kc & 1;
        if (kc + 1 < NCH) asm volatile("cp.async.wait_group 1;" ::: "memory");
        else              asm volatile("cp.async.wait_group 0;" ::: "memory");
        __syncthreads();
        if (kc + 1 < NCH) stsA(1 - cur, ar);
        if (kc + 2 < NCH) ldgA(kc + 2, ar);

        // ---- MMA over buf[cur] ----
        const uint32_t aBase = sb + cur * SST;
        const uint32_t bBase = aBase + 2 * ROWS * 80;
#pragma unroll
        for (int ks = 0; ks < 2; ks++) {
            const uint32_t kb = lh * 16 + ks * 32;
            uint32_t ahi[2][4], alo[2][4];
#pragma unroll
            for (int mt = 0; mt < 2; mt++) {
                uint32_t ad = aBase + (uint32_t)(wm * 32 + mt * 16 + l16) * 80 + kb;
                ldsm_x4(ahi[mt], ad);
                ldsm_x4(alo[mt], ad + ROWS * 80);
            }
#pragma unroll
            for (int ntp = 0; ntp < 4; ntp++) {
                uint32_t bd = bBase + (uint32_t)(wn * 64 + ntp * 16 + l16) * 80 + kb;
                uint32_t bh[4], bl[4];
                ldsm_x4(bh, bd);
                ldsm_x4(bl, bd + N * 80);
#pragma unroll
                for (int mt = 0; mt < 2; mt++) {
#pragma unroll
                    for (int sub = 0; sub < 2; sub++) {
                        int nt = ntp * 2 + sub;
                        mma16816(acc[mt][nt], ahi[mt], bh[sub], bh[sub + 2]);
                        mma16816(acc[mt][nt], ahi[mt], bl[sub], bl[sub + 2]);
                        mma16816(acc[mt][nt], alo[mt], bh[sub], bh[sub + 2]);
                    }
                }
            }
        }
        __syncthreads();
        if (kc + 2 < NCH) { cpB(kc + 2, cur); cp_commit(); }
    }

    // ------------------------- LN epilogue -------------------------
    float* red_s  = reinterpret_cast<float*>(smem);
    float* red_s2 = red_s + 512;
    float* red_d  = red_s2 + 512;

    const int q = lane >> 2, ln3 = lane & 3;

    // bias add into acc; per-row partial sums
    float s[2][2] = {{0.f,0.f},{0.f,0.f}}, s2[2][2] = {{0.f,0.f},{0.f,0.f}};
#pragma unroll
    for (int nt = 0; nt < 8; nt++) {
        int col = wn * 64 + nt * 8 + ln3 * 2;
        float2 bv = *reinterpret_cast<const float2*>(bias + col);
#pragma unroll
        for (int mt = 0; mt < 2; mt++) {
            acc[mt][nt][0] += bv.x; acc[mt][nt][1] += bv.y;
            acc[mt][nt][2] += bv.x; acc[mt][nt][3] += bv.y;
            s [mt][0] += acc[mt][nt][0] + acc[mt][nt][1];
            s2[mt][0] += acc[mt][nt][0]*acc[mt][nt][0] + acc[mt][nt][1]*acc[mt][nt][1];
            s [mt][1] += acc[mt][nt][2] + acc[mt][nt][3];
            s2[mt][1] += acc[mt][nt][2]*acc[mt][nt][2] + acc[mt][nt][3]*acc[mt][nt][3];
        }
    }
#pragma unroll
    for (int mt = 0; mt < 2; mt++)
#pragma unroll
        for (int h = 0; h < 2; h++) {
            s [mt][h] += __shfl_xor_sync(0xffffffffu, s [mt][h], 1);
            s [mt][h] += __shfl_xor_sync(0xffffffffu, s [mt][h], 2);
            s2[mt][h] += __shfl_xor_sync(0xffffffffu, s2[mt][h], 1);
            s2[mt][h] += __shfl_xor_sync(0xffffffffu, s2[mt][h], 2);
        }
    if (ln3 == 0) {
#pragma unroll
        for (int mt = 0; mt < 2; mt++)
#pragma unroll
            for (int h = 0; h < 2; h++) {
                int row = wm * 32 + mt * 16 + h * 8 + q;
                red_s [row * WN + wn] = s [mt][h];
                red_s2[row * WN + wn] = s2[mt][h];
            }
    }
    __syncthreads();
    float mean[2][2], rstd[2][2];
#pragma unroll
    for (int mt = 0; mt < 2; mt++)
#pragma unroll
        for (int h = 0; h < 2; h++) {
            int row = wm * 32 + mt * 16 + h * 8 + q;
            float S = 0.f, S2 = 0.f;
#pragma unroll
            for (int w = 0; w < WN; w++) { S += red_s[row * WN + w]; S2 += red_s2[row * WN + w]; }
            float m = S * (1.f / N);
            float v = S2 * (1.f / N) - m * m;
            mean[mt][h] = m;
            rstd[mt][h] = rsqrtf(v + 1e-5f);
        }

    float dot[2][2] = {{0.f,0.f},{0.f,0.f}};
#pragma unroll
    for (int nt = 0; nt < 8; nt++) {
        int col = wn * 64 + nt * 8 + ln3 * 2;
        float2 gv = *reinterpret_cast<const float2*>(gamma + col);
        float2 bv = *reinterpret_cast<const float2*>(beta + col);
        float2 av = (EPI == 1) ? *reinterpret_cast<const float2*>(a2w + col)
                               : make_float2(0.f, 0.f);
#pragma unroll
        for (int mt = 0; mt < 2; mt++) {
#pragma unroll
            for (int h = 0; h < 2; h++) {
                float y0 = (acc[mt][nt][2*h]   - mean[mt][h]) * rstd[mt][h] * gv.x + bv.x;
                float y1 = (acc[mt][nt][2*h+1] - mean[mt][h]) * rstd[mt][h] * gv.y + bv.y;
                if (EPI <= 1) { y0 = fmaxf(y0, 0.f); y1 = fmaxf(y1, 0.f); }
                if (EPI == 1) {
                    dot[mt][h] += y0 * av.x + y1 * av.y;
                } else {
                    int row = wm * 32 + mt * 16 + h * 8 + q;
                    *reinterpret_cast<float2*>(Y + (size_t)(r0 + row) * N + col) =
                        make_float2(y0, y1);
                }
            }
        }
    }
    if (EPI == 1) {
#pragma unroll
        for (int mt = 0; mt < 2; mt++)
#pragma unroll
            for (int h = 0; h < 2; h++) {
                dot[mt][h] += __shfl_xor_sync(0xffffffffu, dot[mt][h], 1);
                dot[mt][h] += __shfl_xor_sync(0xffffffffu, dot[mt][h], 2);
            }
        if (ln3 == 0) {
#pragma unroll
            for (int mt = 0; mt < 2; mt++)
#pragma unroll
                for (int h = 0; h < 2; h++) {
                    int row = wm * 32 + mt * 16 + h * 8 + q;
                    red_d[row * WN + wn] = dot[mt][h];
                }
        }
        __syncthreads();
        if (wn == 0 && ln3 == 0) {
            float a2b0 = a2b[0];
#pragma unroll
            for (int mt = 0; mt < 2; mt++)
#pragma unroll
                for (int h = 0; h < 2; h++) {
                    int row = wm * 32 + mt * 16 + h * 8 + q;
                    float D = 0.f;
#pragma unroll
                    for (int w = 0; w < WN; w++) D += red_d[row * WN + w];
                    D += a2b0;
                    Y[r0 + row] = 1.f / (1.f + expf(-D));
                }
        }
    }
}

// ---------------------------------------------------------------------------
// Segment-sum / refinement kernels (unchanged — verified in R1)
// ---------------------------------------------------------------------------
__global__ __launch_bounds__(256) void zero_seg_kernel()
{
    int i = blockIdx.x * 256 + threadIdx.x;
    if (i < NSEG * Hc) g_fsum[i] = 0.f;
    if (i < NSEG * Mc) g_asum[i] = 0.f;
    if (i < NSEG)      g_cnt[i]  = 0.f;
}

__global__ __launch_bounds__(256)
void seg_sum_kernel(const int* __restrict__ sp, const float* __restrict__ attn)
{
    int bp = blockIdx.x;
    int b = bp / NPc, p = bp - b * NPc;
    int sid = sp[bp];
    int seg = (sid >= 0) ? (sid + b * Sc) : (Bc * Sc);
    int t = threadIdx.x;
    atomicAdd(&g_fsum[seg * Hc + t], g_pp[(size_t)bp * Hc + t]);
    if (t == 0) atomicAdd(&g_cnt[seg], 1.f);
    if (t < Mc) atomicAdd(&g_asum[seg * Mc + t], attn[((size_t)(b * Mc + t)) * NPc + p]);
}

__global__ __launch_bounds__(256)
void refine_weighted_kernel(const int* __restrict__ sp, const float* __restrict__ vf)
{
    int bp = blockIdx.x;
    int b = bp / NPc, p = bp - b * NPc;
    int t = threadIdx.x;
    int lane = t & 31, wid = t >> 5;
    int sid = sp[bp];
    bool valid = sid >= 0;
    int seg = valid ? (sid + b * Sc) : (Bc * Sc);
    float cnt = fmaxf(g_cnt[seg], 1.f);
    float inv = 1.f / cnt;

    float f  = g_pp[(size_t)bp * Hc + t];
    float fm = g_fsum[seg * Hc + t] * inv;
    float d = f * fm, nf = f * f, nm = fm * fm;
#pragma unroll
    for (int o = 16; o > 0; o >>= 1) {
        d  += __shfl_xor_sync(0xffffffffu, d,  o);
        nf += __shfl_xor_sync(0xffffffffu, nf, o);
        nm += __shfl_xor_sync(0xffffffffu, nm, o);
    }
    __shared__ float sd[8], sf[8], sn[8];
    __shared__ float wts[Mc];
    if (lane == 0) { sd[wid] = d; sf[wid] = nf; sn[wid] = nm; }
    __syncthreads();
    if (t == 0) {
        float D = 0.f, F = 0.f, Nm = 0.f;
#pragma unroll
        for (int i = 0; i < 8; i++) { D += sd[i]; F += sf[i]; Nm += sn[i]; }
        float sim = D / (fmaxf(sqrtf(F), 1e-8f) * fmaxf(sqrtf(Nm), 1e-8f));
        float rv[Mc];
        float mx = -1e30f;
#pragma unroll
        for (int m = 0; m < Mc; m++) {
            float a  = g_attn[((size_t)(b * Mc + m)) * NPc + p];
            float am = g_asum[seg * Mc + m] * inv;
            float rf = valid ? (am + (a - am) * sim) : a;
            rv[m] = rf;
            mx = fmaxf(mx, rf);
        }
        float ssum = 0.f;
#pragma unroll
        for (int m = 0; m < Mc; m++) { rv[m] = expf(rv[m] - mx); ssum += rv[m]; }
        float is = 1.f / ssum;
#pragma unroll
        for (int m = 0; m < Mc; m++) wts[m] = rv[m] * is;
    }
    __syncthreads();

    float acc = 0.f;
#pragma unroll
    for (int m = 0; m < Mc; m++)
        acc += wts[m] * vf[((size_t)(b * Mc + m) * NPc + p) * 256 + t];
    g_weighted[(size_t)bp * Hc + t] = acc;
}

// ---------------------------------------------------------------------------
// Launch
// ---------------------------------------------------------------------------
extern "C" void kernel_launch(void* const* d_in, const int* in_sizes, int n_in,
                              void* d_out, int out_size)
{
    (void)in_sizes; (void)n_in; (void)out_size;
    const float* pf   = (const float*)d_in[0];
    const float* vf   = (const float*)d_in[1];
    const int*   spid = (const int*)d_in[2];
    const float* p_W  = (const float*)d_in[3];
    const float* p_b  = (const float*)d_in[4];
    const float* p_g  = (const float*)d_in[5];
    const float* p_be = (const float*)d_in[6];
    const float* v_W  = (const float*)d_in[7];
    const float* v_b  = (const float*)d_in[8];
    const float* v_g  = (const float*)d_in[9];
    const float* v_be = (const float*)d_in[10];
    const float* a1_W = (const float*)d_in[11];
    const float* a1_b = (const float*)d_in[12];
    const float* a_g  = (const float*)d_in[13];
    const float* a_be = (const float*)d_in[14];
    const float* a2_W = (const float*)d_in[15];
    const float* a2_b = (const float*)d_in[16];
    const float* f_W  = (const float*)d_in[17];
    const float* f_b  = (const float*)d_in[18];
    const float* f_g  = (const float*)d_in[19];
    const float* f_be = (const float*)d_in[20];
    float* out = (float*)d_out;

    float *pp, *vp, *attn, *weighted, *wvp;
    cudaGetSymbolAddress((void**)&pp,       g_pp);
    cudaGetSymbolAddress((void**)&vp,       g_vp);
    cudaGetSymbolAddress((void**)&attn,     g_attn);
    cudaGetSymbolAddress((void**)&weighted, g_weighted);
    cudaGetSymbolAddress((void**)&wvp,      g_wvp);
    __half *pWh, *pWl, *vWh, *vWl, *a1h, *a1l, *fWh, *fWl;
    cudaGetSymbolAddress((void**)&pWh, g_pWT_hi);  cudaGetSymbolAddress((void**)&pWl, g_pWT_lo);
    cudaGetSymbolAddress((void**)&vWh, g_vWT_hi);  cudaGetSymbolAddress((void**)&vWl, g_vWT_lo);
    cudaGetSymbolAddress((void**)&a1h, g_a1WT_hi); cudaGetSymbolAddress((void**)&a1l, g_a1WT_lo);
    cudaGetSymbolAddress((void**)&fWh, g_fWT_hi);  cudaGetSymbolAddress((void**)&fWl, g_fWT_lo);

    // smem: (2*ROWS + 2*N) * 80 bytes per stage, 2 stages
    constexpr int SM_N256 = 2 * (2 * 128 + 2 * 256) * 80;   // 122880
    constexpr int SM_N512 = 2 * (2 * 64 + 2 * 512) * 80;    // 184320
    cudaFuncSetAttribute(mma_gemm_ln<256, 256, 0, false>,
                         cudaFuncAttributeMaxDynamicSharedMemorySize, SM_N256);
    cudaFuncSetAttribute(mma_gemm_ln<256, 512, 1, true>,
                         cudaFuncAttributeMaxDynamicSharedMemorySize, SM_N256);
    cudaFuncSetAttribute(mma_gemm_ln<512, 512, 2, false>,
                         cudaFuncAttributeMaxDynamicSharedMemorySize, SM_N512);

    // 0) weight prep (transpose + fp16 hi/lo split)
    wt_prep<256, 256><<<256, 256>>>(p_W,  pWh, pWl);
    wt_prep<256, 256><<<256, 256>>>(v_W,  vWh, vWl);
    wt_prep<512, 256><<<512, 256>>>(a1_W, a1h, a1l);
    wt_prep<512, 512><<<1024, 256>>>(f_W, fWh, fWl);

    // 1) pp = relu(LN(pf @ p_W + p_b))
    mma_gemm_ln<256, 256, 0, false><<<BNP / 128, 512, SM_N256>>>(
        pf, nullptr, pWh, pWl, p_b, p_g, p_be, nullptr, nullptr, pp);
    // 2) vp = relu(LN(vf @ v_W + v_b))
    mma_gemm_ln<256, 256, 0, false><<<BMNP / 128, 512, SM_N256>>>(
        vf, nullptr, vWh, vWl, v_b, v_g, v_be, nullptr, nullptr, vp);
    // 3) attn = sigmoid(relu(LN([pp,vp] @ a1_W + a1_b)) . a2_W + a2_b)
    mma_gemm_ln<256, 512, 1, true><<<BMNP / 128, 512, SM_N256>>>(
        pp, vp, a1h, a1l, a1_b, a_g, a_be, a2_W, a2_b, attn);
    // 4) segment sums
    zero_seg_kernel<<<(NSEG * Hc + 255) / 256, 256>>>();
    seg_sum_kernel<<<BNP, 256>>>(spid, attn);
    // 5) refine + softmax + weighted view pooling
    refine_weighted_kernel<<<BNP, 256>>>(spid, vf);
    // 6) wvp = relu(LN(weighted @ v_W + v_b))
    mma_gemm_ln<256, 256, 0, false><<<BNP / 128, 512, SM_N256>>>(
        weighted, nullptr, vWh, vWl, v_b, v_g, v_be, nullptr, nullptr, wvp);
    // 7) Z = LN([pp,wvp] @ f_W + f_b)  -> output
    mma_gemm_ln<512, 512, 2, false><<<BNP / 64, 512, SM_N512>>>(
        pp, wvp, fWh, fWl, f_b, f_g, f_be, nullptr, nullptr, out);
}